// round 5
// baseline (speedup 1.0000x reference)
#include <cuda_runtime.h>
#include <cstdint>

// Problem constants (fixed by the reference: B=2, G=64)
constexpr int G3       = 64 * 64 * 64;          // 262144 voxels per batch
constexpr int NB       = 2;
constexpr int THREADS  = 256;
constexpr int NPAIRS   = NB * G3 / 2;           // 262144 voxel pairs
constexpr int NCHUNKS  = NPAIRS / THREADS;      // 1024 chunks of 256 pairs
constexpr int NCTA     = 296;                   // ~2 CTAs per SM, grid-stride

// Packed f32x2 ops (PTX-only; ptxas never auto-fuses FFMA2 from C++).
__device__ __forceinline__ uint64_t fma2(uint64_t a, uint64_t b, uint64_t c) {
    uint64_t d;
    asm("fma.rn.f32x2 %0, %1, %2, %3;" : "=l"(d) : "l"(a), "l"(b), "l"(c));
    return d;
}
__device__ __forceinline__ uint64_t mul2(uint64_t a, uint64_t b) {
    uint64_t d;
    asm("mul.rn.f32x2 %0, %1, %2;" : "=l"(d) : "l"(a), "l"(b));
    return d;
}
__device__ __forceinline__ uint32_t smem_u32(const void* p) {
    uint32_t r;
    asm("{ .reg .u64 t; cvta.to.shared.u64 t, %1; cvt.u32.u64 %0, t; }"
        : "=r"(r) : "l"(p));
    return r;
}

// C_ijkl[b,v] = sum_{mnop} a[b,m,i,v] a[b,n,j,v] a[b,o,k,v] a[b,p,l,v] C0[mnop]
// Persistent CTAs, cp.async double-buffered A staging (per-thread-private smem
// slices), packed f32x2 math, i-loop kept rolled to bound register pressure.
__global__ __launch_bounds__(THREADS, 2)
void alphaC0_42C_kernel(const float* __restrict__ a,
                        const float* __restrict__ c0,
                        float* __restrict__ out)
{
    __shared__ uint64_t sc0[81];
    __shared__ uint64_t sA[2][9][THREADS];   // 2 x 18 KB double buffer

    const int tid = threadIdx.x;
    if (tid < 81) {
        float c = c0[tid];
        float2 cc = make_float2(c, c);
        sc0[tid] = *reinterpret_cast<uint64_t*>(&cc);
    }
    __syncthreads();

    // Issue the 9 cp.async (8 B each) for this thread's pair of chunk c.
    auto issue_chunk = [&](int c, int p) {
        const long pr = (long)c * THREADS + tid;   // global pair index
        const long v2 = pr * 2;
        const int  b  = (int)(v2 / G3);
        const long v  = v2 - (long)b * G3;
        const float* src = a + (long)b * 9 * G3 + v;
#pragma unroll
        for (int mi = 0; mi < 9; ++mi) {
            uint32_t dst = smem_u32(&sA[p][mi][tid]);
            asm volatile("cp.async.ca.shared.global [%0], [%1], 8;\n"
                         :: "r"(dst), "l"(src + (long)mi * G3) : "memory");
        }
    };

    int c = blockIdx.x;
    int p = 0;
    if (c < NCHUNKS) issue_chunk(c, 0);
    asm volatile("cp.async.commit_group;\n" ::: "memory");

    for (; c < NCHUNKS; c += NCTA) {
        const int cn = c + NCTA;
        if (cn < NCHUNKS) issue_chunk(cn, p ^ 1);      // prefetch next
        asm volatile("cp.async.commit_group;\n" ::: "memory");
        asm volatile("cp.async.wait_group 1;\n" ::: "memory");  // chunk c ready
        __syncthreads();   // safety; slices are per-thread private anyway

        // Pull this thread's 3x3 matrix (both voxels) into registers.
        uint64_t A[9];
#pragma unroll
        for (int mi = 0; mi < 9; ++mi) A[mi] = sA[p][mi][tid];

        const long pr = (long)c * THREADS + tid;
        const long v2 = pr * 2;
        const int  b  = (int)(v2 / G3);
        const long v  = v2 - (long)b * G3;
        float* ob = out + (long)b * 81 * G3 + v;

#pragma unroll 1   // rolled: bounds register pressure (R3 spilled when unrolled)
        for (int i = 0; i < 3; ++i) {
            // Stage 1: T1[n,o,p] = sum_m A[m,i] * C0[m,n,o,p]
            uint64_t T1[27];
#pragma unroll
            for (int nop = 0; nop < 27; ++nop) {
                uint64_t s = mul2(A[0 * 3 + i], sc0[nop]);
                s = fma2(A[1 * 3 + i], sc0[27 + nop], s);
                s = fma2(A[2 * 3 + i], sc0[54 + nop], s);
                T1[nop] = s;
            }
#pragma unroll
            for (int j = 0; j < 3; ++j) {
                // Stage 2: T2[o,p] = sum_n A[n,j] * T1[n,o,p]
                uint64_t T2[9];
#pragma unroll
                for (int op = 0; op < 9; ++op) {
                    uint64_t s = mul2(A[0 * 3 + j], T1[op]);
                    s = fma2(A[1 * 3 + j], T1[9 + op], s);
                    s = fma2(A[2 * 3 + j], T1[18 + op], s);
                    T2[op] = s;
                }
#pragma unroll
                for (int k = 0; k < 3; ++k) {
                    // Stage 3: T3[p] = sum_o A[o,k] * T2[o,p]
                    uint64_t T3[3];
#pragma unroll
                    for (int pq = 0; pq < 3; ++pq) {
                        uint64_t s = mul2(A[0 * 3 + k], T2[pq]);
                        s = fma2(A[1 * 3 + k], T2[3 + pq], s);
                        s = fma2(A[2 * 3 + k], T2[6 + pq], s);
                        T3[pq] = s;
                    }
#pragma unroll
                    for (int l = 0; l < 3; ++l) {
                        // Stage 4: C[i,j,k,l] = sum_p A[p,l] * T3[p]
                        uint64_t r = mul2(A[0 * 3 + l], T3[0]);
                        r = fma2(A[1 * 3 + l], T3[1], r);
                        r = fma2(A[2 * 3 + l], T3[2], r);
                        // Coalesced STG.64, default L2 write-back (L2 absorbs
                        // the output stream; streaming hints hurt — see R2).
                        *reinterpret_cast<uint64_t*>(
                            ob + (long)(((i * 3 + j) * 3 + k) * 3 + l) * G3) = r;
                    }
                }
            }
        }
        p ^= 1;
    }
}

extern "C" void kernel_launch(void* const* d_in, const int* in_sizes, int n_in,
                              void* d_out, int out_size)
{
    const float* a   = (const float*)d_in[0];   // alphatensor (2,3,3,64,64,64)
    const float* c0  = (const float*)d_in[1];   // C0_4 (3,3,3,3)
    float*       out = (float*)d_out;           // (2,3,3,3,3,64,64,64)

    alphaC0_42C_kernel<<<NCTA, THREADS>>>(a, c0, out);
}

// round 6
// speedup vs baseline: 1.7907x; 1.7907x over previous
#include <cuda_runtime.h>
#include <cstdint>

// Problem constants (fixed by the reference: B=2, G=64)
constexpr int G3      = 64 * 64 * 64;   // 262144 voxels per batch
constexpr int NB      = 2;
constexpr int THREADS = 256;

// Packed f32x2 ops (PTX-only; ptxas never auto-fuses FFMA2 from C++).
__device__ __forceinline__ uint64_t fma2(uint64_t a, uint64_t b, uint64_t c) {
    uint64_t d;
    asm("fma.rn.f32x2 %0, %1, %2, %3;" : "=l"(d) : "l"(a), "l"(b), "l"(c));
    return d;
}
__device__ __forceinline__ uint64_t mul2(uint64_t a, uint64_t b) {
    uint64_t d;
    asm("mul.rn.f32x2 %0, %1, %2;" : "=l"(d) : "l"(a), "l"(b));
    return d;
}

// C_ijkl[b,v] = sum_{mnop} a[b,m,i,v] a[b,n,j,v] a[b,o,k,v] a[b,p,l,v] C0[mnop]
// One thread = one voxel pair (float2 lanes), all three i handled by a ROLLED
// loop (keeps the live set at one i-iteration: ~120 regs, no spills — the
// fully-unrolled fma2 version spilled under a 128 cap in R3, and every reg cap
// so far has cost more in spill DRAM traffic than it bought in occupancy, so:
// NO cap). Packed fma.rn.f32x2 halves FFMA instruction count vs the best
// scalar kernel: ~1400 instr/thread vs ~2500.
__global__ __launch_bounds__(THREADS)
void alphaC0_42C_kernel(const float* __restrict__ a,
                        const float* __restrict__ c0,
                        float* __restrict__ out)
{
    // sc0 splatted to both f32x2 lanes so it is directly an FFMA2 operand.
    __shared__ uint64_t sc0[81];
    if (threadIdx.x < 81) {
        float c = c0[threadIdx.x];
        float2 cc = make_float2(c, c);
        sc0[threadIdx.x] = *reinterpret_cast<uint64_t*>(&cc);
    }
    __syncthreads();

    // Global pair index over the flattened (b, voxel) axis. G3 even -> no
    // pair crosses the batch boundary; NB==2 -> batch select by compare.
    const long pair = (long)blockIdx.x * THREADS + threadIdx.x;
    const long v2   = pair * 2;
    const int  b    = (v2 >= G3) ? 1 : 0;
    const long v    = v2 - (long)b * G3;

    // Load the 3x3 per-voxel matrix a[m][i] for both voxels of the pair.
    const float* ap = a + (long)b * 9 * G3 + v;
    uint64_t A[9];
#pragma unroll
    for (int mi = 0; mi < 9; ++mi)
        A[mi] = *reinterpret_cast<const uint64_t*>(ap + (long)mi * G3);

    float* ob = out + (long)b * 81 * G3 + v;

#pragma unroll 1   // rolled: one-i live set (~120 regs), no spills
    for (int i = 0; i < 3; ++i) {
        // Stage 1: T1[n,o,p] = sum_m A[m,i] * C0[m,n,o,p]
        uint64_t T1[27];
#pragma unroll
        for (int nop = 0; nop < 27; ++nop) {
            uint64_t s = mul2(A[0 * 3 + i], sc0[nop]);
            s = fma2(A[1 * 3 + i], sc0[27 + nop], s);
            s = fma2(A[2 * 3 + i], sc0[54 + nop], s);
            T1[nop] = s;
        }
#pragma unroll
        for (int j = 0; j < 3; ++j) {
            // Stage 2: T2[o,p] = sum_n A[n,j] * T1[n,o,p]
            uint64_t T2[9];
#pragma unroll
            for (int op = 0; op < 9; ++op) {
                uint64_t s = mul2(A[0 * 3 + j], T1[op]);
                s = fma2(A[1 * 3 + j], T1[9 + op], s);
                s = fma2(A[2 * 3 + j], T1[18 + op], s);
                T2[op] = s;
            }
#pragma unroll
            for (int k = 0; k < 3; ++k) {
                // Stage 3: T3[p] = sum_o A[o,k] * T2[o,p]
                uint64_t T3[3];
#pragma unroll
                for (int p = 0; p < 3; ++p) {
                    uint64_t s = mul2(A[0 * 3 + k], T2[p]);
                    s = fma2(A[1 * 3 + k], T2[3 + p], s);
                    s = fma2(A[2 * 3 + k], T2[6 + p], s);
                    T3[p] = s;
                }
#pragma unroll
                for (int l = 0; l < 3; ++l) {
                    // Stage 4: C[i,j,k,l] = sum_p A[p,l] * T3[p]
                    uint64_t r = mul2(A[0 * 3 + l], T3[0]);
                    r = fma2(A[1 * 3 + l], T3[1], r);
                    r = fma2(A[2 * 3 + l], T3[2], r);
                    // Coalesced STG.64, default L2 write-back (streaming
                    // hints hurt — R2 evidence).
                    *reinterpret_cast<uint64_t*>(
                        ob + (long)(((i * 3 + j) * 3 + k) * 3 + l) * G3) = r;
                }
            }
        }
    }
}

extern "C" void kernel_launch(void* const* d_in, const int* in_sizes, int n_in,
                              void* d_out, int out_size)
{
    const float* a   = (const float*)d_in[0];   // alphatensor (2,3,3,64,64,64)
    const float* c0  = (const float*)d_in[1];   // C0_4 (3,3,3,3)
    float*       out = (float*)d_out;           // (2,3,3,3,3,64,64,64)

    const long total_pairs = (long)NB * G3 / 2;            // 262144
    const int  blocks      = (int)(total_pairs / THREADS); // 1024
    alphaC0_42C_kernel<<<blocks, THREADS>>>(a, c0, out);
}

// round 7
// speedup vs baseline: 1.9854x; 1.1087x over previous
#include <cuda_runtime.h>
#include <cstdint>

// Problem constants (fixed by the reference: B=2, G=64)
constexpr int G3      = 64 * 64 * 64;   // 262144 voxels per batch
constexpr int NB      = 2;
constexpr int THREADS = 256;

// Packed f32x2 ops (PTX-only; ptxas never auto-fuses FFMA2 from C++).
__device__ __forceinline__ uint64_t fma2(uint64_t a, uint64_t b, uint64_t c) {
    uint64_t d;
    asm("fma.rn.f32x2 %0, %1, %2, %3;" : "=l"(d) : "l"(a), "l"(b), "l"(c));
    return d;
}
__device__ __forceinline__ uint64_t mul2(uint64_t a, uint64_t b) {
    uint64_t d;
    asm("mul.rn.f32x2 %0, %1, %2;" : "=l"(d) : "l"(a), "l"(b));
    return d;
}
// Un-hoistable LDS: keeps the 81 C0 constants in shared memory instead of
// letting ptxas promote them to ~162 registers (which pinned R6 at 255 regs
// -> 1 CTA/SM -> issue-starved at 2 warps/SMSP).
__device__ __forceinline__ uint64_t lds64(uint32_t saddr) {
    uint64_t d;
    asm volatile("ld.shared.b64 %0, [%1];" : "=l"(d) : "r"(saddr));
    return d;
}
__device__ __forceinline__ uint32_t smem_u32(const void* p) {
    uint32_t r;
    asm("{ .reg .u64 t; cvta.to.shared.u64 t, %1; cvt.u32.u64 %0, t; }"
        : "=r"(r) : "l"(p));
    return r;
}

// C_ijkl[b,v] = sum_{mnop} a[b,m,i,v] a[b,n,j,v] a[b,o,k,v] a[b,p,l,v] C0[mnop]
// One thread = one voxel pair (packed f32x2 lanes), rolled i-loop (one-i live
// set ~120 regs), C0 pinned in shared, 2 CTAs/SM for 16 warps (4/SMSP).
__global__ __launch_bounds__(THREADS, 2)
void alphaC0_42C_kernel(const float* __restrict__ a,
                        const float* __restrict__ c0,
                        float* __restrict__ out)
{
    // sc0 splatted to both f32x2 lanes so it is directly an FFMA2 operand.
    __shared__ uint64_t sc0[81];
    if (threadIdx.x < 81) {
        float c = c0[threadIdx.x];
        float2 cc = make_float2(c, c);
        sc0[threadIdx.x] = *reinterpret_cast<uint64_t*>(&cc);
    }
    __syncthreads();
    const uint32_t sc0_base = smem_u32(sc0);

    // Global pair index over the flattened (b, voxel) axis. G3 even -> no
    // pair crosses the batch boundary; NB==2 -> batch select by compare.
    const long pair = (long)blockIdx.x * THREADS + threadIdx.x;
    const long v2   = pair * 2;
    const int  b    = (v2 >= G3) ? 1 : 0;
    const long v    = v2 - (long)b * G3;

    // Load the 3x3 per-voxel matrix a[m][i] for both voxels of the pair.
    const float* ap = a + (long)b * 9 * G3 + v;
    uint64_t A[9];
#pragma unroll
    for (int mi = 0; mi < 9; ++mi)
        A[mi] = *reinterpret_cast<const uint64_t*>(ap + (long)mi * G3);

    float* ob = out + (long)b * 81 * G3 + v;

#pragma unroll 1   // rolled: one-i live set; unrolling spilled in R3
    for (int i = 0; i < 3; ++i) {
        // Stage 1: T1[n,o,p] = sum_m A[m,i] * C0[m,n,o,p]  (C0 stays in smem)
        uint64_t T1[27];
#pragma unroll
        for (int nop = 0; nop < 27; ++nop) {
            uint64_t s = mul2(A[0 * 3 + i], lds64(sc0_base + nop * 8u));
            s = fma2(A[1 * 3 + i], lds64(sc0_base + (27 + nop) * 8u), s);
            s = fma2(A[2 * 3 + i], lds64(sc0_base + (54 + nop) * 8u), s);
            T1[nop] = s;
        }
#pragma unroll
        for (int j = 0; j < 3; ++j) {
            // Stage 2: T2[o,p] = sum_n A[n,j] * T1[n,o,p]
            uint64_t T2[9];
#pragma unroll
            for (int op = 0; op < 9; ++op) {
                uint64_t s = mul2(A[0 * 3 + j], T1[op]);
                s = fma2(A[1 * 3 + j], T1[9 + op], s);
                s = fma2(A[2 * 3 + j], T1[18 + op], s);
                T2[op] = s;
            }
#pragma unroll
            for (int k = 0; k < 3; ++k) {
                // Stage 3: T3[p] = sum_o A[o,k] * T2[o,p]
                uint64_t T3[3];
#pragma unroll
                for (int p = 0; p < 3; ++p) {
                    uint64_t s = mul2(A[0 * 3 + k], T2[p]);
                    s = fma2(A[1 * 3 + k], T2[3 + p], s);
                    s = fma2(A[2 * 3 + k], T2[6 + p], s);
                    T3[p] = s;
                }
#pragma unroll
                for (int l = 0; l < 3; ++l) {
                    // Stage 4: C[i,j,k,l] = sum_p A[p,l] * T3[p]
                    uint64_t r = mul2(A[0 * 3 + l], T3[0]);
                    r = fma2(A[1 * 3 + l], T3[1], r);
                    r = fma2(A[2 * 3 + l], T3[2], r);
                    // Coalesced STG.64, default L2 write-back (streaming
                    // hints hurt — R2 evidence).
                    *reinterpret_cast<uint64_t*>(
                        ob + (long)(((i * 3 + j) * 3 + k) * 3 + l) * G3) = r;
                }
            }
        }
    }
}

extern "C" void kernel_launch(void* const* d_in, const int* in_sizes, int n_in,
                              void* d_out, int out_size)
{
    const float* a   = (const float*)d_in[0];   // alphatensor (2,3,3,64,64,64)
    const float* c0  = (const float*)d_in[1];   // C0_4 (3,3,3,3)
    float*       out = (float*)d_out;           // (2,3,3,3,3,64,64,64)

    const long total_pairs = (long)NB * G3 / 2;            // 262144
    const int  blocks      = (int)(total_pairs / THREADS); // 1024
    alphaC0_42C_kernel<<<blocks, THREADS>>>(a, c0, out);
}